// round 5
// baseline (speedup 1.0000x reference)
#include <cuda_runtime.h>
#include <math.h>

#define NTOK 1024
#define DK   128
#define DAPP 2048
#define DG   128

// Scratch (no cudaMalloc allowed)
__device__ float g_q [NTOK*DK];
__device__ float g_k [NTOK*DK];
__device__ float g_vt[DK*NTOK];     // V transposed: vt[d][m]
__device__ float g_sd[NTOK*NTOK];   // scaled dot QK^T/sqrt(dk)
__device__ float g_p [NTOK*NTOK];   // softmax probabilities

// ---------------------------------------------------------------------------
// Init: bias-seed q,k,vt (split-K GEMMs accumulate on top), zero final out.
// ---------------------------------------------------------------------------
__global__ void init_kernel(float* __restrict__ out,
                            const float* __restrict__ qb,
                            const float* __restrict__ kb,
                            const float* __restrict__ vb)
{
    int idx = blockIdx.x * blockDim.x + threadIdx.x;
    if (idx < NTOK * DK) {
        int d = idx & (DK - 1);
        g_q[idx]  = qb[d];
        g_k[idx]  = kb[d];
        g_vt[idx] = vb[idx >> 10];   // vt[d][m], d = idx/1024
        out[idx]  = 0.0f;
    }
}

// ---------------------------------------------------------------------------
// Row-by-row GEMM: C[m][n] = alpha * sum_k A[m][k] * B[n][k]  (+init value)
// BM=64, BN=128, BK=16, 128 threads, 8x8 register micro-tile.
// ATOMIC=1 -> atomicAdd (split-K over blockIdx.z), else direct store.
// TRANSC=1 -> store C[n*ldc + m].
// ---------------------------------------------------------------------------
template<int ATOMIC, int TRANSC>
__global__ __launch_bounds__(128)
void gemm_rr(const float* __restrict__ A, int lda,
             const float* __restrict__ B, int ldb,
             float* __restrict__ C, int ldc,
             int kchunk, float alpha)
{
    __shared__ float As[16][64];    // [k][m]
    __shared__ float Bs[16][128];   // [k][n]

    const int tid = threadIdx.x;
    const int m0  = blockIdx.x * 64;
    const int n0  = blockIdx.y * 128;
    const int kbeg = blockIdx.z * kchunk;
    const int kend = kbeg + kchunk;

    const int rg = tid >> 4;   // 0..7  -> rows m0 + rg*8 + i
    const int cg = tid & 15;   // 0..15 -> cols n0 + cg*8 + j

    float acc[8][8];
#pragma unroll
    for (int i = 0; i < 8; i++)
#pragma unroll
        for (int j = 0; j < 8; j++) acc[i][j] = 0.0f;

    for (int kt = kbeg; kt < kend; kt += 16) {
        // Load A tile 64x16 -> As[k][m] (256 float4 by 128 threads)
#pragma unroll
        for (int i = 0; i < 2; i++) {
            int fid = tid * 2 + i;
            int row = fid >> 2, c4 = fid & 3;
            float4 v = *(const float4*)(A + (size_t)(m0 + row) * lda + kt + c4 * 4);
            As[c4*4+0][row] = v.x; As[c4*4+1][row] = v.y;
            As[c4*4+2][row] = v.z; As[c4*4+3][row] = v.w;
        }
        // Load B tile 128x16 -> Bs[k][n] (512 float4 by 128 threads)
#pragma unroll
        for (int i = 0; i < 4; i++) {
            int fid = tid * 4 + i;
            int row = fid >> 2, c4 = fid & 3;
            float4 v = *(const float4*)(B + (size_t)(n0 + row) * ldb + kt + c4 * 4);
            Bs[c4*4+0][row] = v.x; Bs[c4*4+1][row] = v.y;
            Bs[c4*4+2][row] = v.z; Bs[c4*4+3][row] = v.w;
        }
        __syncthreads();

#pragma unroll
        for (int kk = 0; kk < 16; kk++) {
            float a[8], b[8];
            *(float4*)&a[0] = *(const float4*)&As[kk][rg * 8];
            *(float4*)&a[4] = *(const float4*)&As[kk][rg * 8 + 4];
            *(float4*)&b[0] = *(const float4*)&Bs[kk][cg * 8];
            *(float4*)&b[4] = *(const float4*)&Bs[kk][cg * 8 + 4];
#pragma unroll
            for (int i = 0; i < 8; i++)
#pragma unroll
                for (int j = 0; j < 8; j++)
                    acc[i][j] += a[i] * b[j];
        }
        __syncthreads();
    }

#pragma unroll
    for (int i = 0; i < 8; i++) {
#pragma unroll
        for (int j = 0; j < 8; j++) {
            int m = m0 + rg * 8 + i;
            int n = n0 + cg * 8 + j;
            float v = alpha * acc[i][j];
            int idx = TRANSC ? (n * ldc + m) : (m * ldc + n);
            if (ATOMIC) atomicAdd(&C[idx], v);
            else        C[idx] = v;
        }
    }
}

// ---------------------------------------------------------------------------
// Fused geometric bias + row softmax.
// One block per row m. Each thread streams 512B-contiguous pos_emb chunks
// (dot with wg in smem), adds scaled-dot, then block softmax -> P row.
// ---------------------------------------------------------------------------
__global__ __launch_bounds__(256)
void geo_softmax(const float* __restrict__ pos,
                 const float* __restrict__ wg,
                 const float* __restrict__ wgb)
{
    __shared__ float s[NTOK];
    __shared__ float wgs[DG];
    __shared__ float red[8];
    __shared__ float bcast;

    const int tid = threadIdx.x;
    const int m   = blockIdx.x;

    if (tid < DG) wgs[tid] = wg[tid];
    const float gb = wgb[0];
    __syncthreads();

    const float* rowp  = pos + (size_t)m * NTOK * DG;
    const float* sdrow = g_sd + (size_t)m * NTOK;

    for (int n = tid; n < NTOK; n += 256) {
        const float4* g = (const float4*)(rowp + (size_t)n * DG);
        float acc0 = 0.0f, acc1 = 0.0f;
#pragma unroll
        for (int j = 0; j < 32; j += 2) {
            float4 a = g[j];
            float4 b = g[j + 1];
            acc0 += a.x*wgs[4*j+0] + a.y*wgs[4*j+1] + a.z*wgs[4*j+2] + a.w*wgs[4*j+3];
            acc1 += b.x*wgs[4*j+4] + b.y*wgs[4*j+5] + b.z*wgs[4*j+6] + b.w*wgs[4*j+7];
        }
        float geo = acc0 + acc1 + gb;
        s[n] = sdrow[n] + fmaxf(geo, 0.0f);
    }
    __syncthreads();

    // ---- max ----
    float lm = -INFINITY;
    for (int n = tid; n < NTOK; n += 256) lm = fmaxf(lm, s[n]);
#pragma unroll
    for (int o = 16; o > 0; o >>= 1) lm = fmaxf(lm, __shfl_xor_sync(0xFFFFFFFFu, lm, o));
    if ((tid & 31) == 0) red[tid >> 5] = lm;
    __syncthreads();
    if (tid == 0) {
        float mm = red[0];
#pragma unroll
        for (int i = 1; i < 8; i++) mm = fmaxf(mm, red[i]);
        bcast = mm;
    }
    __syncthreads();
    const float rmax = bcast;
    __syncthreads();  // protect red[] reuse

    // ---- exp & sum ----
    float ls = 0.0f;
    for (int n = tid; n < NTOK; n += 256) {
        float e = __expf(s[n] - rmax);
        s[n] = e;
        ls += e;
    }
#pragma unroll
    for (int o = 16; o > 0; o >>= 1) ls += __shfl_xor_sync(0xFFFFFFFFu, ls, o);
    if ((tid & 31) == 0) red[tid >> 5] = ls;
    __syncthreads();
    if (tid == 0) {
        float ss = red[0];
#pragma unroll
        for (int i = 1; i < 8; i++) ss += red[i];
        bcast = ss;
    }
    __syncthreads();
    const float inv = 1.0f / bcast;

    float* prow = g_p + (size_t)m * NTOK;
    for (int n = tid; n < NTOK; n += 256)
        prow[n] = s[n] * inv;
}

// ---------------------------------------------------------------------------
extern "C" void kernel_launch(void* const* d_in, const int* in_sizes, int n_in,
                              void* d_out, int out_size)
{
    const float* app = (const float*)d_in[0];
    const float* pos = (const float*)d_in[1];
    const float* wqw = (const float*)d_in[2];
    const float* wqb = (const float*)d_in[3];
    const float* wkw = (const float*)d_in[4];
    const float* wkb = (const float*)d_in[5];
    const float* wvw = (const float*)d_in[6];
    const float* wvb = (const float*)d_in[7];
    const float* wgw = (const float*)d_in[8];
    const float* wgb = (const float*)d_in[9];
    float* out = (float*)d_out;

    float *q, *k, *vt, *sd, *p;
    cudaGetSymbolAddress((void**)&q,  g_q);
    cudaGetSymbolAddress((void**)&k,  g_k);
    cudaGetSymbolAddress((void**)&vt, g_vt);
    cudaGetSymbolAddress((void**)&sd, g_sd);
    cudaGetSymbolAddress((void**)&p,  g_p);

    // 1) bias seed + zero out
    init_kernel<<<(NTOK*DK + 255) / 256, 256>>>(out, wqb, wkb, wvb);

    // 2) Q/K/V projections: 1024x128 = app(1024x2048) . W^T, split-K=8 (kchunk 256)
    gemm_rr<1,0><<<dim3(16,1,8), 128>>>(app, DAPP, wqw, DAPP, q,  DK,   256, 1.0f);
    gemm_rr<1,0><<<dim3(16,1,8), 128>>>(app, DAPP, wkw, DAPP, k,  DK,   256, 1.0f);
    gemm_rr<1,1><<<dim3(16,1,8), 128>>>(app, DAPP, wvw, DAPP, vt, NTOK, 256, 1.0f);

    // 3) scaled dot: sd = q.k^T / sqrt(128)
    gemm_rr<0,0><<<dim3(16,8,1), 128>>>(q, DK, k, DK, sd, NTOK, 128,
                                        0.088388347648318447f);

    // 4) geometric bias + softmax -> P
    geo_softmax<<<NTOK, 256>>>(pos, wgw, wgb);

    // 5) out = P . V  (V stored transposed -> row.row), split-K=8 (kchunk 128)
    gemm_rr<1,0><<<dim3(16,1,8), 128>>>(p, NTOK, vt, NTOK, out, DK, 128, 1.0f);
}